// round 8
// baseline (speedup 1.0000x reference)
#include <cuda_runtime.h>
#include <cuda_fp16.h>
#include <cstdint>

#define NPTS 65536
#define NE 8
#define DIN 90
#define NH 256
#define DOUT 4
#define XROW 93
#define TILE_P 128
#define KPAD 96
#define THREADS 128
#define GRID_P 148

// smem byte offsets (strides 208B=13*16, 528B=33*16 -> ldmatrix conflict-free)
#define SH_W1   0           // W1T [256][104h]    53,248B
#define SH_W2   53248       // W2T [256][264h]   135,168B
#define SH_W3T  188416      // W3T [16][264h]      8,448B (rows 0-3 data, 4-15 zero)
#define SH_F    196864      // F   [128][104h]    26,624B
#define SH_B1   223488      // b1 f32 [256]
#define SH_B2   224512      // b2 f32 [256]
#define SH_B3   225536      // b3 f32 [4]
#define SH_IDX  225552      // idx [2][128] int
#define SMEM_BYTES 226576

// -------- device scratch --------
__device__ float  g_w[NPTS * NE];
__device__ int    g_idx[NE * NPTS];
__device__ int    g_cnt[NE];
__device__ __half g_xh[NPTS * KPAD];
__device__ __half g_w1t[NE * NH * KPAD];
__device__ __half g_w2t[NE * NH * NH];

#define WCONV_TOTAL (NE * NH * KPAD + NE * NH * NH)

// -------- PTX helpers --------
__device__ __forceinline__ uint32_t smem_u32(const void* p) {
    uint32_t a;
    asm("{ .reg .u64 t; cvta.to.shared.u64 t, %1; cvt.u32.u64 %0, t; }" : "=r"(a) : "l"(p));
    return a;
}
__device__ __forceinline__ void ldsm4(uint32_t& r0, uint32_t& r1, uint32_t& r2, uint32_t& r3,
                                      uint32_t addr) {
    asm volatile("ldmatrix.sync.aligned.m8n8.x4.shared.b16 {%0,%1,%2,%3}, [%4];"
                 : "=r"(r0), "=r"(r1), "=r"(r2), "=r"(r3) : "r"(addr));
}
__device__ __forceinline__ void mma16816(float* c, const uint32_t* a, uint32_t b0, uint32_t b1) {
    asm volatile(
        "mma.sync.aligned.m16n8k16.row.col.f32.f16.f16.f32 "
        "{%0,%1,%2,%3}, {%4,%5,%6,%7}, {%8,%9}, {%0,%1,%2,%3};"
        : "+f"(c[0]), "+f"(c[1]), "+f"(c[2]), "+f"(c[3])
        : "r"(a[0]), "r"(a[1]), "r"(a[2]), "r"(a[3]), "r"(b0), "r"(b1));
}
__device__ __forceinline__ void cpa16(uint32_t dst, const void* src) {
    asm volatile("cp.async.cg.shared.global [%0], [%1], 16;" :: "r"(dst), "l"(src));
}
__device__ __forceinline__ void cpa_commit() { asm volatile("cp.async.commit_group;"); }
__device__ __forceinline__ void cpa_wait0() { asm volatile("cp.async.wait_group 0;" ::: "memory"); }
__device__ __forceinline__ uint32_t pack2(float a, float b) {
    __half2 h = __floats2half2_rn(a, b);
    return *(uint32_t*)&h;
}

// -------- kernel 0: counters --------
__global__ void zero_cnt_kernel() {
    if (threadIdx.x < NE) g_cnt[threadIdx.x] = 0;
}

// -------- kernel 1: routing + compaction + out zero + x fp16 convert --------
__global__ void routing_kernel(const float* __restrict__ x,
                               const float* __restrict__ cent,
                               float* __restrict__ out) {
    int n = blockIdx.x * blockDim.x + threadIdx.x;
    if (n >= NPTS) return;
    const float px = x[n * XROW + 0];
    const float py = x[n * XROW + 1];
    const float pz = x[n * XROW + 2];
    float d[NE];
    float dmin = 3.4e38f;
#pragma unroll
    for (int e = 0; e < NE; e++) {
        float dx = px - cent[e * 3 + 0];
        float dy = py - cent[e * 3 + 1];
        float dz = pz - cent[e * 3 + 2];
        d[e] = sqrtf(dx * dx + dy * dy + dz * dz);
        dmin = fminf(dmin, d[e]);
    }
    float inv[NE];
    float s = 0.f;
#pragma unroll
    for (int e = 0; e < NE; e++) {
        float v = 1.0f / (d[e] + 1e-8f);
        if (d[e] > 2.0f * dmin) v = 0.f;
        inv[e] = v;
        s += v;
    }
    float rs = 1.0f / s;
#pragma unroll
    for (int e = 0; e < NE; e++) {
        float w = inv[e] * rs;
        g_w[n * NE + e] = w;
        if (w > 0.f) {
            int pos = atomicAdd(&g_cnt[e], 1);
            g_idx[e * NPTS + pos] = n;
        }
    }
    *reinterpret_cast<float4*>(out + n * 4) = make_float4(0.f, 0.f, 0.f, 0.f);

    // fp16 convert of this point's features (row-local, unit stride)
    const float* xr = x + (size_t)n * XROW + 3;
    __half2* dst = (__half2*)(g_xh + (size_t)n * KPAD);
#pragma unroll
    for (int kp = 0; kp < 45; kp++) dst[kp] = __floats2half2_rn(xr[2 * kp], xr[2 * kp + 1]);
#pragma unroll
    for (int kp = 45; kp < 48; kp++) dst[kp] = __floats2half2_rn(0.f, 0.f);
}

// -------- kernel 1b: weight fp16 pre-convert (W1T, W2T) --------
__global__ void wconvert_kernel(const float* __restrict__ W1,
                                const float* __restrict__ W2) {
    int i = blockIdx.x * blockDim.x + threadIdx.x;
    if (i < NE * NH * KPAD) {
        int e = i / (NH * KPAD);
        int rr = i - e * NH * KPAD;
        int n = rr / KPAD, k = rr - n * KPAD;
        g_w1t[i] = (k < DIN) ? __float2half_rn(W1[(e * DIN + k) * NH + n]) : __half(0.f);
    } else if (i < WCONV_TOTAL) {
        int r = i - NE * NH * KPAD;
        int e = r >> 16;
        int rr = r & 65535;
        int n = rr >> 8, k = rr & 255;
        g_w2t[r] = __float2half_rn(W2[(e << 16) + (k << 8) + n]);
    }
}

// -------- tile prefetch: idx + F rows via cp.async --------
__device__ __forceinline__ void prefetch_tile(uint32_t A0, char* smb, int e, int base,
                                              int cnt, int ibuf, int t) {
    int gi = base + t;
    int idxv = (gi < cnt) ? g_idx[e * NPTS + gi] : -1;
    ((int*)(smb + SH_IDX))[ibuf * TILE_P + t] = idxv;
    int real = idxv < 0 ? 0 : idxv;
    const char* src = (const char*)(g_xh + (size_t)real * KPAD);
    uint32_t dst = A0 + SH_F + t * 208;
#pragma unroll
    for (int j = 0; j < 12; j++) cpa16(dst + j * 16, src + j * 16);
}

// -------- expert weight load --------
__device__ __forceinline__ void load_expert(uint32_t A0, char* smb, int e, int t,
                                            const float* b1, const float* b2,
                                            const float* W3, const float* b3) {
#pragma unroll
    for (int rr = 0; rr < 2; rr++) {
        int n = t + rr * THREADS;
        {
            const char* src = (const char*)(g_w1t + ((size_t)e * NH + n) * KPAD);
            uint32_t dst = A0 + SH_W1 + n * 208;
#pragma unroll
            for (int j = 0; j < 12; j++) cpa16(dst + j * 16, src + j * 16);
        }
        {
            const char* src = (const char*)(g_w2t + ((size_t)e * NH + n) * NH);
            uint32_t dst = A0 + SH_W2 + n * 528;
#pragma unroll
            for (int j = 0; j < 32; j++) cpa16(dst + j * 16, src + j * 16);
        }
    }
    if (t < 64) cpa16(A0 + SH_B1 + t * 16, (const char*)(b1 + e * NH) + t * 16);
    else cpa16(A0 + SH_B2 + (t - 64) * 16, (const char*)(b2 + e * NH) + (t - 64) * 16);
    {
        __half* w3t = (__half*)(smb + SH_W3T);
        for (int i = t; i < 12 * 256; i += THREADS) {       // zero rows 4..15
            int r = i >> 8, k = i & 255;
            w3t[(4 + r) * 264 + k] = __half(0.f);
        }
        for (int i = t; i < 4 * 256; i += THREADS) {        // rows 0..3 = W3^T
            int o = i >> 8, k = i & 255;
            w3t[o * 264 + k] = __float2half_rn(W3[e * NH * DOUT + k * DOUT + o]);
        }
    }
    if (t < 4) ((float*)(smb + SH_B3))[t] = b3[e * DOUT + t];
}

// -------- kernel 2: persistent fused MLP (4 warps, m32/warp) --------
__global__ __launch_bounds__(THREADS, 1)
void mlp_persist_kernel(const float* __restrict__ b1, const float* __restrict__ b2,
                        const float* __restrict__ W3, const float* __restrict__ b3,
                        float* __restrict__ out) {
    int tp[NE + 1];
    {
        int run = 0;
#pragma unroll
        for (int e = 0; e < NE; e++) {
            tp[e] = run;
            run += (g_cnt[e] + TILE_P - 1) / TILE_P;
        }
        tp[NE] = run;
    }
    const int total = tp[NE];
    const int G = gridDim.x;
    const int lo = (int)(((long long)blockIdx.x * total) / G);
    const int hi = (int)(((long long)(blockIdx.x + 1) * total) / G);
    if (lo >= hi) return;

    extern __shared__ char smb[];
    const uint32_t A0 = smem_u32(smb);
    const int t = threadIdx.x;
    const int wid = t >> 5, lane = t & 31;
    const int g = lane >> 2, tg = lane & 3;
    const int m0 = wid * 32;

    const uint32_t rowpat = (uint32_t)((lane & 7) + ((lane >> 4) << 3));
    const uint32_t colpat = (uint32_t)(((lane >> 3) & 1) * 16);
    const uint32_t bRow1 = A0 + SH_W1 + rowpat * 208 + colpat;
    const uint32_t bRow2 = A0 + SH_W2 + rowpat * 528 + colpat;
    const uint32_t wRow3 = A0 + SH_W3T + rowpat * 528 + colpat;
    const uint32_t aPat = (uint32_t)(lane & 15) * 208 + (uint32_t)(lane >> 4) * 16;

    int cur_e = -1;
    int cbuf = 0;
    {
        int e0 = 0;
#pragma unroll
        for (int k = 1; k < NE; k++) if (lo >= tp[k]) e0 = k;
        prefetch_tile(A0, smb, e0, (lo - tp[e0]) * TILE_P, g_cnt[e0], 0, t);
        cpa_commit();
    }

    for (int tt = lo; tt < hi; tt++) {
        int e = 0;
#pragma unroll
        for (int k = 1; k < NE; k++) if (tt >= tp[k]) e = k;

        cpa_wait0();
        __syncthreads();                       // F(tt)+idx ready
        if (e != cur_e) {
            load_expert(A0, smb, e, t, b1, b2, W3, b3);
            cpa_commit();
            cpa_wait0();
            __syncthreads();
            cur_e = e;
        }

        // ---- layer 1: two m16 passes -> hA[2][64] fp16 A-fragments ----
        uint32_t hA[2][64];
#pragma unroll
        for (int p = 0; p < 2; p++) {
            const uint32_t aBase = A0 + SH_F + (uint32_t)(m0 + 16 * p) * 208 + aPat;
            uint32_t A1[6][4];
#pragma unroll
            for (int s = 0; s < 6; s++)
                ldsm4(A1[s][0], A1[s][1], A1[s][2], A1[s][3], aBase + s * 32);
#pragma unroll
            for (int qpp = 0; qpp < 8; qpp++) {
                float C[16];
#pragma unroll
                for (int i = 0; i < 16; i++) C[i] = 0.f;
                uint32_t bbA = bRow1 + (qpp * 32) * 208;
                uint32_t bbB = bbA + 16 * 208;
                uint32_t bf[2][8];
                ldsm4(bf[0][0], bf[0][1], bf[0][2], bf[0][3], bbA);
                ldsm4(bf[0][4], bf[0][5], bf[0][6], bf[0][7], bbB);
#pragma unroll
                for (int s = 0; s < 6; s++) {
                    int cu = s & 1;
                    if (s < 5) {
                        ldsm4(bf[cu ^ 1][0], bf[cu ^ 1][1], bf[cu ^ 1][2], bf[cu ^ 1][3],
                              bbA + (s + 1) * 32);
                        ldsm4(bf[cu ^ 1][4], bf[cu ^ 1][5], bf[cu ^ 1][6], bf[cu ^ 1][7],
                              bbB + (s + 1) * 32);
                    }
                    mma16816(C + 0,  A1[s], bf[cu][0], bf[cu][1]);
                    mma16816(C + 4,  A1[s], bf[cu][2], bf[cu][3]);
                    mma16816(C + 8,  A1[s], bf[cu][4], bf[cu][5]);
                    mma16816(C + 12, A1[s], bf[cu][6], bf[cu][7]);
                }
#pragma unroll
                for (int h = 0; h < 2; h++) {
                    int colb = 32 * qpp + 16 * h;
                    float2 ba = *(float2*)(smb + SH_B1 + (colb + 2 * tg) * 4);
                    float2 bb = *(float2*)(smb + SH_B1 + (colb + 8 + 2 * tg) * 4);
                    const float* Cc = C + 8 * h;
                    hA[p][8 * qpp + 4 * h + 0] = pack2(fmaxf(Cc[0] + ba.x, 0.f), fmaxf(Cc[1] + ba.y, 0.f));
                    hA[p][8 * qpp + 4 * h + 1] = pack2(fmaxf(Cc[2] + ba.x, 0.f), fmaxf(Cc[3] + ba.y, 0.f));
                    hA[p][8 * qpp + 4 * h + 2] = pack2(fmaxf(Cc[4] + bb.x, 0.f), fmaxf(Cc[5] + bb.y, 0.f));
                    hA[p][8 * qpp + 4 * h + 3] = pack2(fmaxf(Cc[6] + bb.x, 0.f), fmaxf(Cc[7] + bb.y, 0.f));
                }
            }
        }
        __syncthreads();                       // F buffer free

        if (tt + 1 < hi) {
            int e2 = 0;
#pragma unroll
            for (int k = 1; k < NE; k++) if (tt + 1 >= tp[k]) e2 = k;
            prefetch_tile(A0, smb, e2, (tt + 1 - tp[e2]) * TILE_P, g_cnt[e2], cbuf ^ 1, t);
            cpa_commit();
        }

        // ---- layer 2 (m32 per warp) + fused layer-3 mma ----
        float C3lo[4] = {0.f, 0.f, 0.f, 0.f};
        float C3hi[4] = {0.f, 0.f, 0.f, 0.f};
#pragma unroll
        for (int qpp = 0; qpp < 8; qpp++) {
            float C[32];
#pragma unroll
            for (int i = 0; i < 32; i++) C[i] = 0.f;
            uint32_t bbA = bRow2 + (qpp * 32) * 528;
            uint32_t bbB = bbA + 16 * 528;
            uint32_t bf[2][8];
            ldsm4(bf[0][0], bf[0][1], bf[0][2], bf[0][3], bbA);
            ldsm4(bf[0][4], bf[0][5], bf[0][6], bf[0][7], bbB);
#pragma unroll
            for (int s = 0; s < 16; s++) {
                int cu = s & 1;
                if (s < 15) {
                    ldsm4(bf[cu ^ 1][0], bf[cu ^ 1][1], bf[cu ^ 1][2], bf[cu ^ 1][3],
                          bbA + (s + 1) * 32);
                    ldsm4(bf[cu ^ 1][4], bf[cu ^ 1][5], bf[cu ^ 1][6], bf[cu ^ 1][7],
                          bbB + (s + 1) * 32);
                }
                mma16816(C + 0,  &hA[0][4 * s], bf[cu][0], bf[cu][1]);
                mma16816(C + 4,  &hA[0][4 * s], bf[cu][2], bf[cu][3]);
                mma16816(C + 8,  &hA[0][4 * s], bf[cu][4], bf[cu][5]);
                mma16816(C + 12, &hA[0][4 * s], bf[cu][6], bf[cu][7]);
                mma16816(C + 16, &hA[1][4 * s], bf[cu][0], bf[cu][1]);
                mma16816(C + 20, &hA[1][4 * s], bf[cu][2], bf[cu][3]);
                mma16816(C + 24, &hA[1][4 * s], bf[cu][4], bf[cu][5]);
                mma16816(C + 28, &hA[1][4 * s], bf[cu][6], bf[cu][7]);
            }
#pragma unroll
            for (int h = 0; h < 2; h++) {
                int colb = 32 * qpp + 16 * h;
                float2 ba = *(float2*)(smb + SH_B2 + (colb + 2 * tg) * 4);
                float2 bb = *(float2*)(smb + SH_B2 + (colb + 8 + 2 * tg) * 4);
                const float* Cl = C + 8 * h;
                const float* Ch = C + 16 + 8 * h;
                uint32_t a2l[4], a2h[4];
                a2l[0] = pack2(fmaxf(Cl[0] + ba.x, 0.f), fmaxf(Cl[1] + ba.y, 0.f));
                a2l[1] = pack2(fmaxf(Cl[2] + ba.x, 0.f), fmaxf(Cl[3] + ba.y, 0.f));
                a2l[2] = pack2(fmaxf(Cl[4] + bb.x, 0.f), fmaxf(Cl[5] + bb.y, 0.f));
                a2l[3] = pack2(fmaxf(Cl[6] + bb.x, 0.f), fmaxf(Cl[7] + bb.y, 0.f));
                a2h[0] = pack2(fmaxf(Ch[0] + ba.x, 0.f), fmaxf(Ch[1] + ba.y, 0.f));
                a2h[1] = pack2(fmaxf(Ch[2] + ba.x, 0.f), fmaxf(Ch[3] + ba.y, 0.f));
                a2h[2] = pack2(fmaxf(Ch[4] + bb.x, 0.f), fmaxf(Ch[5] + bb.y, 0.f));
                a2h[3] = pack2(fmaxf(Ch[6] + bb.x, 0.f), fmaxf(Ch[7] + bb.y, 0.f));
                uint32_t w0, w1r, w2r, w3r;
                ldsm4(w0, w1r, w2r, w3r, wRow3 + (2 * qpp + h) * 32);
                mma16816(C3lo, a2l, w0, w1r);
                mma16816(C3hi, a2h, w0, w1r);
            }
        }

        // ---- weighted scatter (rows m0+g, m0+8+g, m0+16+g, m0+24+g; cols 2tg..) ----
        if (tg < 2) {
            const int* sIdxCur = (const int*)(smb + SH_IDX) + cbuf * TILE_P;
            const float* sb3 = (const float*)(smb + SH_B3);
            int col = 2 * tg;
            float b3a = sb3[col], b3b = sb3[col + 1];
            int n0i = sIdxCur[m0 + g];
            int n1i = sIdxCur[m0 + 8 + g];
            int n2i = sIdxCur[m0 + 16 + g];
            int n3i = sIdxCur[m0 + 24 + g];
            if (n0i >= 0) {
                float w = g_w[n0i * NE + e];
                atomicAdd(&out[n0i * 4 + col],     w * (C3lo[0] + b3a));
                atomicAdd(&out[n0i * 4 + col + 1], w * (C3lo[1] + b3b));
            }
            if (n1i >= 0) {
                float w = g_w[n1i * NE + e];
                atomicAdd(&out[n1i * 4 + col],     w * (C3lo[2] + b3a));
                atomicAdd(&out[n1i * 4 + col + 1], w * (C3lo[3] + b3b));
            }
            if (n2i >= 0) {
                float w = g_w[n2i * NE + e];
                atomicAdd(&out[n2i * 4 + col],     w * (C3hi[0] + b3a));
                atomicAdd(&out[n2i * 4 + col + 1], w * (C3hi[1] + b3b));
            }
            if (n3i >= 0) {
                float w = g_w[n3i * NE + e];
                atomicAdd(&out[n3i * 4 + col],     w * (C3hi[2] + b3a));
                atomicAdd(&out[n3i * 4 + col + 1], w * (C3hi[3] + b3b));
            }
        }
        cbuf ^= 1;
    }
}

// -------- launch --------
extern "C" void kernel_launch(void* const* d_in, const int* in_sizes, int n_in,
                              void* d_out, int out_size) {
    const float* x    = (const float*)d_in[0];
    const float* cent = (const float*)d_in[1];
    const float* W1   = (const float*)d_in[2];
    const float* b1   = (const float*)d_in[3];
    const float* W2   = (const float*)d_in[4];
    const float* b2   = (const float*)d_in[5];
    const float* W3   = (const float*)d_in[6];
    const float* b3   = (const float*)d_in[7];
    float* out = (float*)d_out;

    cudaFuncSetAttribute(mlp_persist_kernel, cudaFuncAttributeMaxDynamicSharedMemorySize,
                         SMEM_BYTES);

    zero_cnt_kernel<<<1, 32>>>();
    routing_kernel<<<NPTS / 256, 256>>>(x, cent, out);
    wconvert_kernel<<<(WCONV_TOTAL + 255) / 256, 256>>>(W1, W2);
    mlp_persist_kernel<<<GRID_P, THREADS, SMEM_BYTES>>>(b1, b2, W3, b3, out);
}

// round 9
// speedup vs baseline: 1.1327x; 1.1327x over previous
#include <cuda_runtime.h>
#include <cuda_fp16.h>
#include <cstdint>

#define NPTS 65536
#define NE 8
#define DIN 90
#define NH 256
#define DOUT 4
#define XROW 93
#define TILE_P 128
#define KPAD 96
#define THREADS 512
#define GRID_P 148

// smem byte offsets (row strides 208B=13*16, 528B=33*16 -> ldmatrix conflict-free)
#define SH_W2   0           // W2T [256][264h]          135,168B (expert-resident)
#define SH_U    135168      // union region, 79,872B:
                            //   W1T [256][104h] at +0 (53,248B, per tile)
                            //   F   [128][104h] at +53,248 (26,624B, per tile)
                            //   H1  [128][264h] overlays [0,67,584) after layer 1
                            //   partials [4][128][4] f32 at +0 after layer 2
#define SH_F    (SH_U + 53248)
#define SH_H1   SH_U
#define SH_PART SH_U
#define SH_W3T  215040      // W3T [16][264h] 8,448B (rows 0-3 data, 4-15 zero)
#define SH_B1   223488      // b1 f32 [256]
#define SH_B2   224512      // b2 f32 [256]
#define SH_B3   225536      // b3 f32 [4]
#define SH_IDX  225552      // idx [128] int
#define SMEM_BYTES 226112

// -------- device scratch --------
__device__ float  g_w[NPTS * NE];
__device__ int    g_idx[NE * NPTS];
__device__ int    g_cnt[NE];
__device__ __half g_xh[NPTS * KPAD];
__device__ __half g_w1t[NE * NH * KPAD];
__device__ __half g_w2t[NE * NH * NH];

#define WCONV_TOTAL (NE * NH * KPAD + NE * NH * NH)

// -------- PTX helpers --------
__device__ __forceinline__ uint32_t smem_u32(const void* p) {
    uint32_t a;
    asm("{ .reg .u64 t; cvta.to.shared.u64 t, %1; cvt.u32.u64 %0, t; }" : "=r"(a) : "l"(p));
    return a;
}
__device__ __forceinline__ void ldsm4(uint32_t& r0, uint32_t& r1, uint32_t& r2, uint32_t& r3,
                                      uint32_t addr) {
    asm volatile("ldmatrix.sync.aligned.m8n8.x4.shared.b16 {%0,%1,%2,%3}, [%4];"
                 : "=r"(r0), "=r"(r1), "=r"(r2), "=r"(r3) : "r"(addr));
}
__device__ __forceinline__ void mma16816(float* c, const uint32_t* a, uint32_t b0, uint32_t b1) {
    asm volatile(
        "mma.sync.aligned.m16n8k16.row.col.f32.f16.f16.f32 "
        "{%0,%1,%2,%3}, {%4,%5,%6,%7}, {%8,%9}, {%0,%1,%2,%3};"
        : "+f"(c[0]), "+f"(c[1]), "+f"(c[2]), "+f"(c[3])
        : "r"(a[0]), "r"(a[1]), "r"(a[2]), "r"(a[3]), "r"(b0), "r"(b1));
}
__device__ __forceinline__ void cpa16(uint32_t dst, const void* src) {
    asm volatile("cp.async.cg.shared.global [%0], [%1], 16;" :: "r"(dst), "l"(src));
}
__device__ __forceinline__ void cpa_commit() { asm volatile("cp.async.commit_group;"); }
__device__ __forceinline__ void cpa_wait0() { asm volatile("cp.async.wait_group 0;" ::: "memory"); }
__device__ __forceinline__ uint32_t pack2(float a, float b) {
    __half2 h = __floats2half2_rn(a, b);
    return *(uint32_t*)&h;
}

// -------- kernel 0: counters --------
__global__ void zero_cnt_kernel() {
    if (threadIdx.x < NE) g_cnt[threadIdx.x] = 0;
}

// -------- kernel 1: routing + compaction + out zero + x fp16 convert --------
__global__ void routing_kernel(const float* __restrict__ x,
                               const float* __restrict__ cent,
                               float* __restrict__ out) {
    int n = blockIdx.x * blockDim.x + threadIdx.x;
    if (n >= NPTS) return;
    const float px = x[n * XROW + 0];
    const float py = x[n * XROW + 1];
    const float pz = x[n * XROW + 2];
    float d[NE];
    float dmin = 3.4e38f;
#pragma unroll
    for (int e = 0; e < NE; e++) {
        float dx = px - cent[e * 3 + 0];
        float dy = py - cent[e * 3 + 1];
        float dz = pz - cent[e * 3 + 2];
        d[e] = sqrtf(dx * dx + dy * dy + dz * dz);
        dmin = fminf(dmin, d[e]);
    }
    float inv[NE];
    float s = 0.f;
#pragma unroll
    for (int e = 0; e < NE; e++) {
        float v = 1.0f / (d[e] + 1e-8f);
        if (d[e] > 2.0f * dmin) v = 0.f;
        inv[e] = v;
        s += v;
    }
    float rs = 1.0f / s;
#pragma unroll
    for (int e = 0; e < NE; e++) {
        float w = inv[e] * rs;
        g_w[n * NE + e] = w;
        if (w > 0.f) {
            int pos = atomicAdd(&g_cnt[e], 1);
            g_idx[e * NPTS + pos] = n;
        }
    }
    *reinterpret_cast<float4*>(out + n * 4) = make_float4(0.f, 0.f, 0.f, 0.f);

    const float* xr = x + (size_t)n * XROW + 3;
    __half2* dst = (__half2*)(g_xh + (size_t)n * KPAD);
#pragma unroll
    for (int kp = 0; kp < 45; kp++) dst[kp] = __floats2half2_rn(xr[2 * kp], xr[2 * kp + 1]);
#pragma unroll
    for (int kp = 45; kp < 48; kp++) dst[kp] = __floats2half2_rn(0.f, 0.f);
}

// -------- kernel 1b: weight fp16 pre-convert (W1T, W2T) --------
__global__ void wconvert_kernel(const float* __restrict__ W1,
                                const float* __restrict__ W2) {
    int i = blockIdx.x * blockDim.x + threadIdx.x;
    if (i < NE * NH * KPAD) {
        int e = i / (NH * KPAD);
        int rr = i - e * NH * KPAD;
        int n = rr / KPAD, k = rr - n * KPAD;
        g_w1t[i] = (k < DIN) ? __float2half_rn(W1[(e * DIN + k) * NH + n]) : __half(0.f);
    } else if (i < WCONV_TOTAL) {
        int r = i - NE * NH * KPAD;
        int e = r >> 16;
        int rr = r & 65535;
        int n = rr >> 8, k = rr & 255;
        g_w2t[r] = __float2half_rn(W2[(e << 16) + (k << 8) + n]);
    }
}

// -------- per-tile load: idx + F + W1T --------
__device__ __forceinline__ void load_tile(uint32_t A0, char* smb, int e, int base,
                                          int cnt, int t) {
    if (t < TILE_P) {
        int gi = base + t;
        int idxv = (gi < cnt) ? g_idx[e * NPTS + gi] : -1;
        ((int*)(smb + SH_IDX))[t] = idxv;
        int real = idxv < 0 ? 0 : idxv;
        const char* src = (const char*)(g_xh + (size_t)real * KPAD);
        uint32_t dst = A0 + SH_F + t * 208;
#pragma unroll
        for (int j = 0; j < 12; j++) cpa16(dst + j * 16, src + j * 16);
    }
    {
        int n = t >> 1;
        int h = (t & 1) * 96;
        const char* src = (const char*)(g_w1t + ((size_t)e * NH + n) * KPAD) + h;
        uint32_t dst = A0 + SH_U + n * 208 + h;
#pragma unroll
        for (int j = 0; j < 6; j++) cpa16(dst + j * 16, src + j * 16);
    }
}

// -------- expert-resident load: W2T + W3T + biases --------
__device__ __forceinline__ void load_expert(uint32_t A0, char* smb, int e, int t,
                                            const float* b1, const float* b2,
                                            const float* W3, const float* b3) {
    {
        int n = t >> 1;
        int h = (t & 1) * 256;
        const char* src = (const char*)(g_w2t + ((size_t)e * NH + n) * NH) + h;
        uint32_t dst = A0 + SH_W2 + n * 528 + h;
#pragma unroll
        for (int j = 0; j < 16; j++) cpa16(dst + j * 16, src + j * 16);
    }
    if (t < 64) cpa16(A0 + SH_B1 + t * 16, (const char*)(b1 + e * NH) + t * 16);
    else if (t < 128) cpa16(A0 + SH_B2 + (t - 64) * 16, (const char*)(b2 + e * NH) + (t - 64) * 16);
    {
        __half* w3t = (__half*)(smb + SH_W3T);
        for (int i = t; i < 12 * 256; i += THREADS) {
            int r = i >> 8, k = i & 255;
            w3t[(4 + r) * 264 + k] = __half(0.f);
        }
        for (int i = t; i < 4 * 256; i += THREADS) {
            int o = i >> 8, k = i & 255;
            w3t[o * 264 + k] = __float2half_rn(W3[e * NH * DOUT + k * DOUT + o]);
        }
    }
    if (t < 4) ((float*)(smb + SH_B3))[t] = b3[e * DOUT + t];
}

// -------- kernel 2: persistent fused MLP (16 warps, m32n64/warp) --------
__global__ __launch_bounds__(THREADS, 1)
void mlp_persist_kernel(const float* __restrict__ b1, const float* __restrict__ b2,
                        const float* __restrict__ W3, const float* __restrict__ b3,
                        float* __restrict__ out) {
    int tp[NE + 1];
    {
        int run = 0;
#pragma unroll
        for (int e = 0; e < NE; e++) {
            tp[e] = run;
            run += (g_cnt[e] + TILE_P - 1) / TILE_P;
        }
        tp[NE] = run;
    }
    const int total = tp[NE];
    const int G = gridDim.x;
    const int lo = (int)(((long long)blockIdx.x * total) / G);
    const int hi = (int)(((long long)(blockIdx.x + 1) * total) / G);
    if (lo >= hi) return;

    extern __shared__ char smb[];
    const uint32_t A0 = smem_u32(smb);
    const int t = threadIdx.x;
    const int wid = t >> 5, lane = t & 31;
    const int g = lane >> 2, tg = lane & 3;
    const int mg = wid & 3, ng = wid >> 2;
    const int m0 = mg * 32, n0 = ng * 64;

    const uint32_t rowpat = (uint32_t)((lane & 7) + ((lane >> 4) << 3));
    const uint32_t colpat = (uint32_t)(((lane >> 3) & 1) * 16);
    const uint32_t aPatF = (uint32_t)(lane & 15) * 208 + (uint32_t)(lane >> 4) * 16;
    const uint32_t aPatH = (uint32_t)(lane & 15) * 528 + (uint32_t)(lane >> 4) * 16;
    const uint32_t bRow1 = A0 + SH_U + (n0 + rowpat) * 208 + colpat;      // W1T strip
    const uint32_t bRow2 = A0 + SH_W2 + (n0 + rowpat) * 528 + colpat;     // W2T strip
    const uint32_t wRow3 = A0 + SH_W3T + rowpat * 528 + colpat;

    int cur_e = -1;

    for (int tt = lo; tt < hi; tt++) {
        int e = 0;
#pragma unroll
        for (int k = 1; k < NE; k++) if (tt >= tp[k]) e = k;

        if (e != cur_e) {
            load_expert(A0, smb, e, t, b1, b2, W3, b3);
            cur_e = e;
        }
        load_tile(A0, smb, e, (tt - tp[e]) * TILE_P, g_cnt[e], t);
        cpa_commit();
        cpa_wait0();
        __syncthreads();

        // ---- layer 1: two n32 passes; packed fp16 results in hH[32] ----
        uint32_t hH[32];
#pragma unroll
        for (int npass = 0; npass < 2; npass++) {
            float C[32];
#pragma unroll
            for (int i = 0; i < 32; i++) C[i] = 0.f;
            const uint32_t bb = bRow1 + (npass * 32) * 208;
            const uint32_t aa = A0 + SH_F + m0 * 208 + aPatF;
#pragma unroll
            for (int s = 0; s < 6; s++) {
                uint32_t a0[4], a1[4], b[8];
                ldsm4(a0[0], a0[1], a0[2], a0[3], aa + s * 32);
                ldsm4(a1[0], a1[1], a1[2], a1[3], aa + 16 * 208 + s * 32);
                ldsm4(b[0], b[1], b[2], b[3], bb + s * 32);
                ldsm4(b[4], b[5], b[6], b[7], bb + 16 * 208 + s * 32);
                mma16816(C + 0,  a0, b[0], b[1]);
                mma16816(C + 4,  a0, b[2], b[3]);
                mma16816(C + 8,  a0, b[4], b[5]);
                mma16816(C + 12, a0, b[6], b[7]);
                mma16816(C + 16, a1, b[0], b[1]);
                mma16816(C + 20, a1, b[2], b[3]);
                mma16816(C + 24, a1, b[4], b[5]);
                mma16816(C + 28, a1, b[6], b[7]);
            }
#pragma unroll
            for (int nt = 0; nt < 4; nt++) {
                int colb = n0 + npass * 32 + nt * 8;
                float2 ba = *(float2*)(smb + SH_B1 + (colb + 2 * tg) * 4);
                const float* Cl = C + nt * 4;
                const float* Ch = C + 16 + nt * 4;
                hH[npass * 16 + nt * 4 + 0] = pack2(fmaxf(Cl[0] + ba.x, 0.f), fmaxf(Cl[1] + ba.y, 0.f));
                hH[npass * 16 + nt * 4 + 1] = pack2(fmaxf(Cl[2] + ba.x, 0.f), fmaxf(Cl[3] + ba.y, 0.f));
                hH[npass * 16 + nt * 4 + 2] = pack2(fmaxf(Ch[0] + ba.x, 0.f), fmaxf(Ch[1] + ba.y, 0.f));
                hH[npass * 16 + nt * 4 + 3] = pack2(fmaxf(Ch[2] + ba.x, 0.f), fmaxf(Ch[3] + ba.y, 0.f));
            }
        }
        __syncthreads();                 // all warps done reading F/W1T

        // ---- write H1 (overlays W1T+F) ----
#pragma unroll
        for (int npass = 0; npass < 2; npass++)
#pragma unroll
            for (int nt = 0; nt < 4; nt++)
#pragma unroll
                for (int q = 0; q < 4; q++) {
                    int row = m0 + q * 8 + g;
                    int col = n0 + npass * 32 + nt * 8 + 2 * tg;
                    *(uint32_t*)(smb + SH_H1 + row * 528 + col * 2) =
                        hH[npass * 16 + nt * 4 + q];
                }
        __syncthreads();                 // H1 visible

        // ---- layer 2: m32n64 per warp over k256 ----
        float C2[64];
#pragma unroll
        for (int i = 0; i < 64; i++) C2[i] = 0.f;
        {
            const uint32_t aa = A0 + SH_H1 + m0 * 528 + aPatH;
#pragma unroll
            for (int s = 0; s < 16; s++) {
                uint32_t a0[4], a1[4], b[16];
                ldsm4(a0[0], a0[1], a0[2], a0[3], aa + s * 32);
                ldsm4(a1[0], a1[1], a1[2], a1[3], aa + 16 * 528 + s * 32);
#pragma unroll
                for (int r = 0; r < 4; r++)
                    ldsm4(b[4 * r], b[4 * r + 1], b[4 * r + 2], b[4 * r + 3],
                          bRow2 + r * 16 * 528 + s * 32);
#pragma unroll
                for (int nb = 0; nb < 8; nb++) {
                    mma16816(C2 + nb * 4,      a0, b[2 * nb], b[2 * nb + 1]);
                    mma16816(C2 + 32 + nb * 4, a1, b[2 * nb], b[2 * nb + 1]);
                }
            }
        }

        // ---- epilogue 2: fused layer-3 mma over this warp's j-slice ----
        float C3lo[4] = {0.f, 0.f, 0.f, 0.f};
        float C3hi[4] = {0.f, 0.f, 0.f, 0.f};
#pragma unroll
        for (int qq = 0; qq < 4; qq++) {
            int colb = n0 + qq * 16;
            float2 ba = *(float2*)(smb + SH_B2 + (colb + 2 * tg) * 4);
            float2 bb = *(float2*)(smb + SH_B2 + (colb + 8 + 2 * tg) * 4);
            const float* Cl0 = C2 + (2 * qq) * 4;
            const float* Cl1 = C2 + (2 * qq + 1) * 4;
            const float* Ch0 = C2 + 32 + (2 * qq) * 4;
            const float* Ch1 = C2 + 32 + (2 * qq + 1) * 4;
            uint32_t a2l[4], a2h[4];
            a2l[0] = pack2(fmaxf(Cl0[0] + ba.x, 0.f), fmaxf(Cl0[1] + ba.y, 0.f));
            a2l[1] = pack2(fmaxf(Cl0[2] + ba.x, 0.f), fmaxf(Cl0[3] + ba.y, 0.f));
            a2l[2] = pack2(fmaxf(Cl1[0] + bb.x, 0.f), fmaxf(Cl1[1] + bb.y, 0.f));
            a2l[3] = pack2(fmaxf(Cl1[2] + bb.x, 0.f), fmaxf(Cl1[3] + bb.y, 0.f));
            a2h[0] = pack2(fmaxf(Ch0[0] + ba.x, 0.f), fmaxf(Ch0[1] + ba.y, 0.f));
            a2h[1] = pack2(fmaxf(Ch0[2] + ba.x, 0.f), fmaxf(Ch0[3] + ba.y, 0.f));
            a2h[2] = pack2(fmaxf(Ch1[0] + bb.x, 0.f), fmaxf(Ch1[1] + bb.y, 0.f));
            a2h[3] = pack2(fmaxf(Ch1[2] + bb.x, 0.f), fmaxf(Ch1[3] + bb.y, 0.f));
            uint32_t w0, w1r, w2r, w3r;
            ldsm4(w0, w1r, w2r, w3r, wRow3 + (ng * 4 + qq) * 32);
            mma16816(C3lo, a2l, w0, w1r);
            mma16816(C3hi, a2h, w0, w1r);
        }
        __syncthreads();                 // layer-2 H1 reads done; partials may overlay

        // ---- stage per-(ng) partials ----
        if (tg < 2) {
            float* pp = (float*)(smb + SH_PART);
            int col = 2 * tg;
            int r0 = m0 + g, r1 = m0 + 8 + g, r2 = m0 + 16 + g, r3 = m0 + 24 + g;
            pp[(ng * TILE_P + r0) * 4 + col]     = C3lo[0];
            pp[(ng * TILE_P + r0) * 4 + col + 1] = C3lo[1];
            pp[(ng * TILE_P + r1) * 4 + col]     = C3lo[2];
            pp[(ng * TILE_P + r1) * 4 + col + 1] = C3lo[3];
            pp[(ng * TILE_P + r2) * 4 + col]     = C3hi[0];
            pp[(ng * TILE_P + r2) * 4 + col + 1] = C3hi[1];
            pp[(ng * TILE_P + r3) * 4 + col]     = C3hi[2];
            pp[(ng * TILE_P + r3) * 4 + col + 1] = C3hi[3];
        }
        __syncthreads();

        // ---- final reduce + weighted scatter ----
        {
            const int p = t >> 2, o = t & 3;
            const float* pp = (const float*)(smb + SH_PART);
            float v = ((const float*)(smb + SH_B3))[o];
#pragma unroll
            for (int q = 0; q < 4; q++) v += pp[(q * TILE_P + p) * 4 + o];
            int n = ((const int*)(smb + SH_IDX))[p];
            if (n >= 0) atomicAdd(&out[n * 4 + o], g_w[n * NE + e] * v);
        }
        __syncthreads();                 // partials/idx reads done before next tile load
    }
}

// -------- launch --------
extern "C" void kernel_launch(void* const* d_in, const int* in_sizes, int n_in,
                              void* d_out, int out_size) {
    const float* x    = (const float*)d_in[0];
    const float* cent = (const float*)d_in[1];
    const float* W1   = (const float*)d_in[2];
    const float* b1   = (const float*)d_in[3];
    const float* W2   = (const float*)d_in[4];
    const float* b2   = (const float*)d_in[5];
    const float* W3   = (const float*)d_in[6];
    const float* b3   = (const float*)d_in[7];
    float* out = (float*)d_out;

    cudaFuncSetAttribute(mlp_persist_kernel, cudaFuncAttributeMaxDynamicSharedMemorySize,
                         SMEM_BYTES);

    zero_cnt_kernel<<<1, 32>>>();
    routing_kernel<<<NPTS / 256, 256>>>(x, cent, out);
    wconvert_kernel<<<(WCONV_TOTAL + 255) / 256, 256>>>(W1, W2);
    mlp_persist_kernel<<<GRID_P, THREADS, SMEM_BYTES>>>(b1, b2, W3, b3, out);
}

// round 10
// speedup vs baseline: 1.1641x; 1.0277x over previous
#include <cuda_runtime.h>
#include <cuda_fp16.h>
#include <cstdint>

#define NPTS 65536
#define NE 8
#define DIN 90
#define NH 256
#define DOUT 4
#define XROW 93
#define TILE_P 128
#define KPAD 96
#define THREADS 512
#define GRID_P 148

// smem byte offsets (row strides 208B=13*16, 528B=33*16 -> ldmatrix conflict-free)
#define SH_W2   0           // W2T [256][264h] 135,168B (expert-resident)
#define SH_U    135168      // union 79,872B: W1T [256][104h] @+0 (53,248); F [128][104h] @+53,248
                            //   H1 [128][264h] overlays @+0 (67,584) after layer 1
#define SH_F    (SH_U + 53248)
#define SH_H1   SH_U
#define SH_W3T  215040      // W3T [8][264h] 4,224B (rows 0-3 data, 4-7 zero), ldsm.x2
#define SH_PART 219264      // partials [4][128][4] f32 = 8,192B (dedicated)
#define SH_B1   227456      // b1 f32 [256]
#define SH_B2   228480      // b2 f32 [256]
#define SH_B3   229504      // b3 f32 [4]
#define SH_IDX  229520      // idx [2][128] int
#define SMEM_BYTES 230544

// -------- device scratch --------
__device__ float  g_w[NPTS * NE];
__device__ int    g_idx[NE * NPTS];
__device__ int    g_cnt[NE];
__device__ __half g_xh[NPTS * KPAD];
__device__ __half g_w1t[NE * NH * KPAD];
__device__ __half g_w2t[NE * NH * NH];

#define WCONV_TOTAL (NE * NH * KPAD + NE * NH * NH)

// -------- PTX helpers --------
__device__ __forceinline__ uint32_t smem_u32(const void* p) {
    uint32_t a;
    asm("{ .reg .u64 t; cvta.to.shared.u64 t, %1; cvt.u32.u64 %0, t; }" : "=r"(a) : "l"(p));
    return a;
}
__device__ __forceinline__ void ldsm4(uint32_t& r0, uint32_t& r1, uint32_t& r2, uint32_t& r3,
                                      uint32_t addr) {
    asm volatile("ldmatrix.sync.aligned.m8n8.x4.shared.b16 {%0,%1,%2,%3}, [%4];"
                 : "=r"(r0), "=r"(r1), "=r"(r2), "=r"(r3) : "r"(addr));
}
__device__ __forceinline__ void ldsm2(uint32_t& r0, uint32_t& r1, uint32_t addr) {
    asm volatile("ldmatrix.sync.aligned.m8n8.x2.shared.b16 {%0,%1}, [%2];"
                 : "=r"(r0), "=r"(r1) : "r"(addr));
}
__device__ __forceinline__ void mma16816(float* c, const uint32_t* a, uint32_t b0, uint32_t b1) {
    asm volatile(
        "mma.sync.aligned.m16n8k16.row.col.f32.f16.f16.f32 "
        "{%0,%1,%2,%3}, {%4,%5,%6,%7}, {%8,%9}, {%0,%1,%2,%3};"
        : "+f"(c[0]), "+f"(c[1]), "+f"(c[2]), "+f"(c[3])
        : "r"(a[0]), "r"(a[1]), "r"(a[2]), "r"(a[3]), "r"(b0), "r"(b1));
}
__device__ __forceinline__ void cpa16(uint32_t dst, const void* src) {
    asm volatile("cp.async.cg.shared.global [%0], [%1], 16;" :: "r"(dst), "l"(src));
}
__device__ __forceinline__ void cpa_commit() { asm volatile("cp.async.commit_group;"); }
__device__ __forceinline__ void cpa_wait0() { asm volatile("cp.async.wait_group 0;" ::: "memory"); }
__device__ __forceinline__ uint32_t pack2(float a, float b) {
    __half2 h = __floats2half2_rn(a, b);
    return *(uint32_t*)&h;
}

// -------- kernel 1a: weight fp16 pre-convert (W1T, W2T) + counter zero --------
__global__ void wconvert_kernel(const float* __restrict__ W1,
                                const float* __restrict__ W2) {
    int i = blockIdx.x * blockDim.x + threadIdx.x;
    if (i < NE) g_cnt[i] = 0;
    if (i < NE * NH * KPAD) {
        int e = i / (NH * KPAD);
        int rr = i - e * NH * KPAD;
        int n = rr / KPAD, k = rr - n * KPAD;
        g_w1t[i] = (k < DIN) ? __float2half_rn(W1[(e * DIN + k) * NH + n]) : __half(0.f);
    } else if (i < WCONV_TOTAL) {
        int r = i - NE * NH * KPAD;
        int e = r >> 16;
        int rr = r & 65535;
        int n = rr >> 8, k = rr & 255;
        g_w2t[r] = __float2half_rn(W2[(e << 16) + (k << 8) + n]);
    }
}

// -------- kernel 1b: routing + compaction + out zero + x fp16 convert --------
__global__ void routing_kernel(const float* __restrict__ x,
                               const float* __restrict__ cent,
                               float* __restrict__ out) {
    int n = blockIdx.x * blockDim.x + threadIdx.x;
    if (n >= NPTS) return;
    const float px = x[n * XROW + 0];
    const float py = x[n * XROW + 1];
    const float pz = x[n * XROW + 2];
    float d[NE];
    float dmin = 3.4e38f;
#pragma unroll
    for (int e = 0; e < NE; e++) {
        float dx = px - cent[e * 3 + 0];
        float dy = py - cent[e * 3 + 1];
        float dz = pz - cent[e * 3 + 2];
        d[e] = sqrtf(dx * dx + dy * dy + dz * dz);
        dmin = fminf(dmin, d[e]);
    }
    float inv[NE];
    float s = 0.f;
#pragma unroll
    for (int e = 0; e < NE; e++) {
        float v = 1.0f / (d[e] + 1e-8f);
        if (d[e] > 2.0f * dmin) v = 0.f;
        inv[e] = v;
        s += v;
    }
    float rs = 1.0f / s;
#pragma unroll
    for (int e = 0; e < NE; e++) {
        float w = inv[e] * rs;
        g_w[n * NE + e] = w;
        if (w > 0.f) {
            int pos = atomicAdd(&g_cnt[e], 1);
            g_idx[e * NPTS + pos] = n;
        }
    }
    *reinterpret_cast<float4*>(out + n * 4) = make_float4(0.f, 0.f, 0.f, 0.f);

    const float* xr = x + (size_t)n * XROW + 3;
    __half2* dst = (__half2*)(g_xh + (size_t)n * KPAD);
#pragma unroll
    for (int kp = 0; kp < 45; kp++) dst[kp] = __floats2half2_rn(xr[2 * kp], xr[2 * kp + 1]);
#pragma unroll
    for (int kp = 45; kp < 48; kp++) dst[kp] = __floats2half2_rn(0.f, 0.f);
}

// -------- per-tile prefetch: idx + F + W1T (expert e's) --------
__device__ __forceinline__ void prefetch_tile(uint32_t A0, char* smb, int e, int base,
                                              int cnt, int ibuf, int t) {
    if (t < TILE_P) {
        int gi = base + t;
        int idxv = (gi < cnt) ? g_idx[e * NPTS + gi] : -1;
        ((int*)(smb + SH_IDX))[ibuf * TILE_P + t] = idxv;
        int real = idxv < 0 ? 0 : idxv;
        const char* src = (const char*)(g_xh + (size_t)real * KPAD);
        uint32_t dst = A0 + SH_F + t * 208;
#pragma unroll
        for (int j = 0; j < 12; j++) cpa16(dst + j * 16, src + j * 16);
    }
    {
        int n = t >> 1;
        int h = (t & 1) * 96;
        const char* src = (const char*)(g_w1t + ((size_t)e * NH + n) * KPAD) + h;
        uint32_t dst = A0 + SH_U + n * 208 + h;
#pragma unroll
        for (int j = 0; j < 6; j++) cpa16(dst + j * 16, src + j * 16);
    }
}

// -------- expert-resident load: W2T + W3T + biases --------
__device__ __forceinline__ void load_expert(uint32_t A0, char* smb, int e, int t,
                                            const float* b1, const float* b2,
                                            const float* W3, const float* b3) {
    {
        int n = t >> 1;
        int h = (t & 1) * 256;
        const char* src = (const char*)(g_w2t + ((size_t)e * NH + n) * NH) + h;
        uint32_t dst = A0 + SH_W2 + n * 528 + h;
#pragma unroll
        for (int j = 0; j < 16; j++) cpa16(dst + j * 16, src + j * 16);
    }
    if (t < 64) cpa16(A0 + SH_B1 + t * 16, (const char*)(b1 + e * NH) + t * 16);
    else if (t < 128) cpa16(A0 + SH_B2 + (t - 64) * 16, (const char*)(b2 + e * NH) + (t - 64) * 16);
    {
        __half* w3t = (__half*)(smb + SH_W3T);
        for (int i = t; i < 4 * 256; i += THREADS) {    // zero rows 4..7
            int r = i >> 8, k = i & 255;
            w3t[(4 + r) * 264 + k] = __half(0.f);
        }
        for (int i = t; i < 4 * 256; i += THREADS) {    // rows 0..3 = W3^T
            int o = i >> 8, k = i & 255;
            w3t[o * 264 + k] = __float2half_rn(W3[e * NH * DOUT + k * DOUT + o]);
        }
    }
    if (t < 4) ((float*)(smb + SH_B3))[t] = b3[e * DOUT + t];
}

// -------- kernel 2: persistent fused MLP (16 warps, m32n64/warp, pipelined) --------
__global__ __launch_bounds__(THREADS, 1)
void mlp_persist_kernel(const float* __restrict__ b1, const float* __restrict__ b2,
                        const float* __restrict__ W3, const float* __restrict__ b3,
                        float* __restrict__ out) {
    int tp[NE + 1];
    {
        int run = 0;
#pragma unroll
        for (int e = 0; e < NE; e++) {
            tp[e] = run;
            run += (g_cnt[e] + TILE_P - 1) / TILE_P;
        }
        tp[NE] = run;
    }
    const int total = tp[NE];
    const int G = gridDim.x;
    const int lo = (int)(((long long)blockIdx.x * total) / G);
    const int hi = (int)(((long long)(blockIdx.x + 1) * total) / G);
    if (lo >= hi) return;

    extern __shared__ char smb[];
    const uint32_t A0 = smem_u32(smb);
    const int t = threadIdx.x;
    const int lane = t & 31;
    const int g = lane >> 2, tg = lane & 3;
    const int mg = (t >> 5) & 3, ng = t >> 7;
    const int m0 = mg * 32, n0 = ng * 64;

    const uint32_t rowpat = (uint32_t)((lane & 7) + ((lane >> 4) << 3));
    const uint32_t colpat = (uint32_t)(((lane >> 3) & 1) * 16);
    const uint32_t aPatF = (uint32_t)(lane & 15) * 208 + (uint32_t)(lane >> 4) * 16;
    const uint32_t aPatH = (uint32_t)(lane & 15) * 528 + (uint32_t)(lane >> 4) * 16;
    const uint32_t bRow1 = A0 + SH_U + (n0 + rowpat) * 208 + colpat;
    const uint32_t bRow2 = A0 + SH_W2 + (n0 + rowpat) * 528 + colpat;
    const uint32_t wRow3 = A0 + SH_W3T + (uint32_t)(lane & 7) * 528 + colpat;

    int cur_e = -1;
    int cbuf = 0;
    {
        int e0 = 0;
#pragma unroll
        for (int k = 1; k < NE; k++) if (lo >= tp[k]) e0 = k;
        prefetch_tile(A0, smb, e0, (lo - tp[e0]) * TILE_P, g_cnt[e0], 0, t);
        cpa_commit();
    }

    for (int tt = lo; tt < hi; tt++) {
        int e = 0;
#pragma unroll
        for (int k = 1; k < NE; k++) if (tt >= tp[k]) e = k;

        cpa_wait0();
        __syncthreads();                       // F+W1T(tt)+idx visible
        if (e != cur_e) {
            load_expert(A0, smb, e, t, b1, b2, W3, b3);
            cpa_commit();
            cpa_wait0();
            __syncthreads();
            cur_e = e;
        }

        // ---- layer 1: two n32 passes; B double-buffered; results packed in hH[32] ----
        uint32_t hH[32];
        {
            const uint32_t aa = A0 + SH_F + m0 * 208 + aPatF;
#pragma unroll
            for (int npass = 0; npass < 2; npass++) {
                float C[32];
#pragma unroll
                for (int i = 0; i < 32; i++) C[i] = 0.f;
                const uint32_t bb = bRow1 + (npass * 32) * 208;
                uint32_t bf[2][8];
                ldsm4(bf[0][0], bf[0][1], bf[0][2], bf[0][3], bb);
                ldsm4(bf[0][4], bf[0][5], bf[0][6], bf[0][7], bb + 16 * 208);
#pragma unroll
                for (int s = 0; s < 6; s++) {
                    const int cu = s & 1;
                    if (s < 5) {
                        ldsm4(bf[cu ^ 1][0], bf[cu ^ 1][1], bf[cu ^ 1][2], bf[cu ^ 1][3],
                              bb + (s + 1) * 32);
                        ldsm4(bf[cu ^ 1][4], bf[cu ^ 1][5], bf[cu ^ 1][6], bf[cu ^ 1][7],
                              bb + 16 * 208 + (s + 1) * 32);
                    }
                    uint32_t a0[4], a1[4];
                    ldsm4(a0[0], a0[1], a0[2], a0[3], aa + s * 32);
                    ldsm4(a1[0], a1[1], a1[2], a1[3], aa + 16 * 208 + s * 32);
                    mma16816(C + 0,  a0, bf[cu][0], bf[cu][1]);
                    mma16816(C + 4,  a0, bf[cu][2], bf[cu][3]);
                    mma16816(C + 8,  a0, bf[cu][4], bf[cu][5]);
                    mma16816(C + 12, a0, bf[cu][6], bf[cu][7]);
                    mma16816(C + 16, a1, bf[cu][0], bf[cu][1]);
                    mma16816(C + 20, a1, bf[cu][2], bf[cu][3]);
                    mma16816(C + 24, a1, bf[cu][4], bf[cu][5]);
                    mma16816(C + 28, a1, bf[cu][6], bf[cu][7]);
                }
#pragma unroll
                for (int nt = 0; nt < 4; nt++) {
                    int colb = n0 + npass * 32 + nt * 8;
                    float2 ba = *(float2*)(smb + SH_B1 + (colb + 2 * tg) * 4);
                    const float* Cl = C + nt * 4;
                    const float* Ch = C + 16 + nt * 4;
                    hH[npass * 16 + nt * 4 + 0] = pack2(fmaxf(Cl[0] + ba.x, 0.f), fmaxf(Cl[1] + ba.y, 0.f));
                    hH[npass * 16 + nt * 4 + 1] = pack2(fmaxf(Cl[2] + ba.x, 0.f), fmaxf(Cl[3] + ba.y, 0.f));
                    hH[npass * 16 + nt * 4 + 2] = pack2(fmaxf(Ch[0] + ba.x, 0.f), fmaxf(Ch[1] + ba.y, 0.f));
                    hH[npass * 16 + nt * 4 + 3] = pack2(fmaxf(Ch[2] + ba.x, 0.f), fmaxf(Ch[3] + ba.y, 0.f));
                }
            }
        }
        __syncthreads();                       // all layer-1 reads of F/W1T done

        // ---- write H1 (overlays W1T+F region) ----
#pragma unroll
        for (int npass = 0; npass < 2; npass++)
#pragma unroll
            for (int nt = 0; nt < 4; nt++)
#pragma unroll
                for (int q = 0; q < 4; q++) {
                    int row = m0 + q * 8 + g;
                    int col = n0 + npass * 32 + nt * 8 + 2 * tg;
                    *(uint32_t*)(smb + SH_H1 + row * 528 + col * 2) =
                        hH[npass * 16 + nt * 4 + q];
                }
        __syncthreads();                       // H1 visible

        // ---- layer 2: m32n64 per warp over k256, B double-buffered ----
        float C2[64];
#pragma unroll
        for (int i = 0; i < 64; i++) C2[i] = 0.f;
        {
            const uint32_t aa = A0 + SH_H1 + m0 * 528 + aPatH;
            uint32_t bf[2][16];
#pragma unroll
            for (int r = 0; r < 4; r++)
                ldsm4(bf[0][4 * r], bf[0][4 * r + 1], bf[0][4 * r + 2], bf[0][4 * r + 3],
                      bRow2 + r * 16 * 528);
#pragma unroll
            for (int s = 0; s < 16; s++) {
                const int cu = s & 1;
                if (s < 15) {
#pragma unroll
                    for (int r = 0; r < 4; r++)
                        ldsm4(bf[cu ^ 1][4 * r], bf[cu ^ 1][4 * r + 1],
                              bf[cu ^ 1][4 * r + 2], bf[cu ^ 1][4 * r + 3],
                              bRow2 + r * 16 * 528 + (s + 1) * 32);
                }
                uint32_t a0[4], a1[4];
                ldsm4(a0[0], a0[1], a0[2], a0[3], aa + s * 32);
                ldsm4(a1[0], a1[1], a1[2], a1[3], aa + 16 * 528 + s * 32);
#pragma unroll
                for (int nb = 0; nb < 8; nb++) {
                    mma16816(C2 + nb * 4,      a0, bf[cu][2 * nb], bf[cu][2 * nb + 1]);
                    mma16816(C2 + 32 + nb * 4, a1, bf[cu][2 * nb], bf[cu][2 * nb + 1]);
                }
            }
        }
        __syncthreads();                       // all layer-2 H1 reads done

        // ---- prefetch next tile's F+W1T+idx (flies under epilogue+scatter) ----
        if (tt + 1 < hi) {
            int e2 = 0;
#pragma unroll
            for (int k = 1; k < NE; k++) if (tt + 1 >= tp[k]) e2 = k;
            prefetch_tile(A0, smb, e2, (tt + 1 - tp[e2]) * TILE_P, g_cnt[e2], cbuf ^ 1, t);
            cpa_commit();
        }

        // ---- epilogue 2: bias+relu+pack, fused layer-3 mma ----
        float C3lo[4] = {0.f, 0.f, 0.f, 0.f};
        float C3hi[4] = {0.f, 0.f, 0.f, 0.f};
#pragma unroll
        for (int qq = 0; qq < 4; qq++) {
            int colb = n0 + qq * 16;
            float2 ba = *(float2*)(smb + SH_B2 + (colb + 2 * tg) * 4);
            float2 bb = *(float2*)(smb + SH_B2 + (colb + 8 + 2 * tg) * 4);
            const float* Cl0 = C2 + (2 * qq) * 4;
            const float* Cl1 = C2 + (2 * qq + 1) * 4;
            const float* Ch0 = C2 + 32 + (2 * qq) * 4;
            const float* Ch1 = C2 + 32 + (2 * qq + 1) * 4;
            uint32_t a2l[4], a2h[4];
            a2l[0] = pack2(fmaxf(Cl0[0] + ba.x, 0.f), fmaxf(Cl0[1] + ba.y, 0.f));
            a2l[1] = pack2(fmaxf(Cl0[2] + ba.x, 0.f), fmaxf(Cl0[3] + ba.y, 0.f));
            a2l[2] = pack2(fmaxf(Cl1[0] + bb.x, 0.f), fmaxf(Cl1[1] + bb.y, 0.f));
            a2l[3] = pack2(fmaxf(Cl1[2] + bb.x, 0.f), fmaxf(Cl1[3] + bb.y, 0.f));
            a2h[0] = pack2(fmaxf(Ch0[0] + ba.x, 0.f), fmaxf(Ch0[1] + ba.y, 0.f));
            a2h[1] = pack2(fmaxf(Ch0[2] + ba.x, 0.f), fmaxf(Ch0[3] + ba.y, 0.f));
            a2h[2] = pack2(fmaxf(Ch1[0] + bb.x, 0.f), fmaxf(Ch1[1] + bb.y, 0.f));
            a2h[3] = pack2(fmaxf(Ch1[2] + bb.x, 0.f), fmaxf(Ch1[3] + bb.y, 0.f));
            uint32_t w0, w1r;
            ldsm2(w0, w1r, wRow3 + (ng * 4 + qq) * 32);
            mma16816(C3lo, a2l, w0, w1r);
            mma16816(C3hi, a2h, w0, w1r);
        }

        // ---- stage per-(ng) partials (dedicated region) ----
        if (tg < 2) {
            float* pp = (float*)(smb + SH_PART);
            int col = 2 * tg;
            int r0 = m0 + g, r1 = m0 + 8 + g, r2 = m0 + 16 + g, r3 = m0 + 24 + g;
            pp[(ng * TILE_P + r0) * 4 + col]     = C3lo[0];
            pp[(ng * TILE_P + r0) * 4 + col + 1] = C3lo[1];
            pp[(ng * TILE_P + r1) * 4 + col]     = C3lo[2];
            pp[(ng * TILE_P + r1) * 4 + col + 1] = C3lo[3];
            pp[(ng * TILE_P + r2) * 4 + col]     = C3hi[0];
            pp[(ng * TILE_P + r2) * 4 + col + 1] = C3hi[1];
            pp[(ng * TILE_P + r3) * 4 + col]     = C3hi[2];
            pp[(ng * TILE_P + r3) * 4 + col + 1] = C3hi[3];
        }
        __syncthreads();

        // ---- final reduce + weighted scatter ----
        {
            const int p = t >> 2, o = t & 3;
            const float* pp = (const float*)(smb + SH_PART);
            float v = ((const float*)(smb + SH_B3))[o];
#pragma unroll
            for (int q = 0; q < 4; q++) v += pp[(q * TILE_P + p) * 4 + o];
            int n = ((const int*)(smb + SH_IDX))[cbuf * TILE_P + p];
            if (n >= 0) atomicAdd(&out[n * 4 + o], g_w[n * NE + e] * v);
        }
        cbuf ^= 1;
    }
}

// -------- launch --------
extern "C" void kernel_launch(void* const* d_in, const int* in_sizes, int n_in,
                              void* d_out, int out_size) {
    const float* x    = (const float*)d_in[0];
    const float* cent = (const float*)d_in[1];
    const float* W1   = (const float*)d_in[2];
    const float* b1   = (const float*)d_in[3];
    const float* W2   = (const float*)d_in[4];
    const float* b2   = (const float*)d_in[5];
    const float* W3   = (const float*)d_in[6];
    const float* b3   = (const float*)d_in[7];
    float* out = (float*)d_out;

    cudaFuncSetAttribute(mlp_persist_kernel, cudaFuncAttributeMaxDynamicSharedMemorySize,
                         SMEM_BYTES);

    wconvert_kernel<<<(WCONV_TOTAL + 255) / 256, 256>>>(W1, W2);
    routing_kernel<<<NPTS / 256, 256>>>(x, cent, out);
    mlp_persist_kernel<<<GRID_P, THREADS, SMEM_BYTES>>>(b1, b2, W3, b3, out);
}